// round 2
// baseline (speedup 1.0000x reference)
#include <cuda_runtime.h>

#define NEG_INF -1.0e9f

// Problem sizes (fixed by the reference)
#define B 8
#define N 512
#define D 256
#define DH 64

// Scratch for Q, K, V projections (allocation-free: __device__ globals)
__device__ float d_Q[B * N * DH];
__device__ float d_K[B * N * DH];
__device__ float d_V[B * N * DH];

// ---------------------------------------------------------------------------
// QKV projection: one block per (b, n) row. 256 threads: stage x row in smem,
// threads 0..191 each compute one output column of Q/K/V (dot over d=256).
// W reads are coalesced (consecutive cols) and L1-resident (64 KB per W).
// ---------------------------------------------------------------------------
__global__ void qkv_kernel(const float* __restrict__ x, const int* __restrict__ mask,
                           const float* __restrict__ Wq, const float* __restrict__ bq,
                           const float* __restrict__ Wk, const float* __restrict__ bk,
                           const float* __restrict__ Wv, const float* __restrict__ bv) {
    int row = blockIdx.x;  // 0..B*N-1
    __shared__ float xs[D];
    int t = threadIdx.x;
    xs[t] = x[row * D + t];
    __syncthreads();
    if (t < 3 * DH) {
        int which = t >> 6;       // 0=Q, 1=K, 2=V
        int col = t & (DH - 1);
        const float* W = (which == 0) ? Wq : (which == 1) ? Wk : Wv;
        const float* Bv = (which == 0) ? bq : (which == 1) ? bk : bv;
        float acc = Bv[col];
#pragma unroll 16
        for (int k = 0; k < D; k++)
            acc = fmaf(xs[k], W[k * DH + col], acc);
        float m = (float)mask[row];
        float* O = (which == 0) ? d_Q : (which == 1) ? d_K : d_V;
        O[row * DH + col] = acc * m;
    }
}

// ---------------------------------------------------------------------------
// Attention: one block per (b, i-tile of 32 rows). 128 blocks total = 1 wave.
// Phase 1: scores S[32][512] into smem, K streamed in 64-row chunks.
// Phase 2: row softmax (unnormalized exp kept in smem, inv-sum per row).
// Phase 3: out = P @ V, V streamed in 64-row chunks, final scale by
//          inv_sum * node_mask[i].
// Thread layout: tx = t&15 (16 cols), ty = t>>4 (16 row-pairs).
// Micro-tile per thread: 2 rows x 4 cols (cols strided tx + 16*c).
// Padded strides (65) keep LDS conflict-free.
// ---------------------------------------------------------------------------
#define BM 32
#define BN 64
#define QS_STRIDE 65
#define KS_STRIDE 65
#define SMEM_FLOATS (BM * QS_STRIDE + BN * KS_STRIDE + BM * N)

__global__ void attn_kernel(const int* __restrict__ mask, float* __restrict__ out) {
    extern __shared__ float sm[];
    float* Qs = sm;                                  // 32*65
    float* Ks = sm + BM * QS_STRIDE;                 // 64*65 (reused for V)
    float* Ss = sm + BM * QS_STRIDE + BN * KS_STRIDE;  // 32*512
    __shared__ float im[BM], jm[BN], rinv[BM];

    int b = blockIdx.x >> 4;
    int i0 = (blockIdx.x & 15) * BM;
    int t = threadIdx.x, tx = t & 15, ty = t >> 4;
    int i_0 = 2 * ty, i_1 = 2 * ty + 1;

    const float* Qb = d_Q + (b * N + i0) * DH;
    const float* Kb = d_K + b * N * DH;
    const float* Vb = d_V + b * N * DH;

    // Load Q tile + row masks
    for (int l = t; l < BM * DH; l += 256) {
        int r = l >> 6, c = l & 63;
        Qs[r * QS_STRIDE + c] = Qb[r * DH + c];
    }
    if (t < BM) im[t] = (float)mask[b * N + i0 + t];
    __syncthreads();

    // ---- Phase 1: scores ----
    for (int jc = 0; jc < N / BN; jc++) {
        int j0 = jc * BN;
        for (int l = t; l < BN * DH; l += 256) {
            int r = l >> 6, c = l & 63;
            Ks[r * KS_STRIDE + c] = Kb[(j0 + r) * DH + c];
        }
        if (t < BN) jm[t] = (float)mask[b * N + j0 + t];
        __syncthreads();

        float a0[4] = {0.f, 0.f, 0.f, 0.f};
        float a1[4] = {0.f, 0.f, 0.f, 0.f};
#pragma unroll 4
        for (int k = 0; k < DH; k++) {
            float q0 = Qs[i_0 * QS_STRIDE + k];
            float q1 = Qs[i_1 * QS_STRIDE + k];
#pragma unroll
            for (int c = 0; c < 4; c++) {
                float kk = Ks[(tx + 16 * c) * KS_STRIDE + k];
                a0[c] = fmaf(q0, kk, a0[c]);
                a1[c] = fmaf(q1, kk, a1[c]);
            }
        }
        float mi0 = im[i_0], mi1 = im[i_1];
#pragma unroll
        for (int c = 0; c < 4; c++) {
            int j = tx + 16 * c;
            float mj = jm[j];
            Ss[i_0 * N + j0 + j] = (mi0 * mj != 0.f) ? a0[c] * 0.125f : NEG_INF;
            Ss[i_1 * N + j0 + j] = (mi1 * mj != 0.f) ? a1[c] * 0.125f : NEG_INF;
        }
        __syncthreads();
    }

    // ---- Phase 2: softmax (keep unnormalized exp, record inv-sum) ----
#pragma unroll
    for (int r = 0; r < 2; r++) {
        int i = 2 * ty + r;
        float mx = NEG_INF;
        for (int cc = 0; cc < N / 16; cc++)
            mx = fmaxf(mx, Ss[i * N + tx + 16 * cc]);
        for (int m = 8; m; m >>= 1)
            mx = fmaxf(mx, __shfl_xor_sync(0xffffffffu, mx, m));
        float s = 0.f;
        for (int cc = 0; cc < N / 16; cc++) {
            float p = __expf(Ss[i * N + tx + 16 * cc] - mx);
            Ss[i * N + tx + 16 * cc] = p;
            s += p;
        }
        for (int m = 8; m; m >>= 1)
            s += __shfl_xor_sync(0xffffffffu, s, m);
        if (tx == 0) rinv[i] = 1.f / s;
    }
    __syncthreads();

    // ---- Phase 3: out = P @ V ----
    float o0[4] = {0.f, 0.f, 0.f, 0.f};
    float o1[4] = {0.f, 0.f, 0.f, 0.f};
    for (int jc = 0; jc < N / BN; jc++) {
        int j0 = jc * BN;
        for (int l = t; l < BN * DH; l += 256) {
            int r = l >> 6, c = l & 63;
            Ks[r * KS_STRIDE + c] = Vb[(j0 + r) * DH + c];
        }
        __syncthreads();
#pragma unroll 4
        for (int jj = 0; jj < BN; jj++) {
            float p0 = Ss[i_0 * N + j0 + jj];
            float p1 = Ss[i_1 * N + j0 + jj];
#pragma unroll
            for (int c = 0; c < 4; c++) {
                float v = Ks[jj * KS_STRIDE + tx + 16 * c];
                o0[c] = fmaf(p0, v, o0[c]);
                o1[c] = fmaf(p1, v, o1[c]);
            }
        }
        __syncthreads();
    }

    float s0 = rinv[i_0] * im[i_0];
    float s1 = rinv[i_1] * im[i_1];
#pragma unroll
    for (int c = 0; c < 4; c++) {
        out[(b * N + i0 + i_0) * DH + tx + 16 * c] = o0[c] * s0;
        out[(b * N + i0 + i_1) * DH + tx + 16 * c] = o1[c] * s1;
    }
}

extern "C" void kernel_launch(void* const* d_in, const int* in_sizes, int n_in,
                              void* d_out, int out_size) {
    const float* x  = (const float*)d_in[0];
    const float* e  = (const float*)d_in[1];
    const int* mask = (const int*)d_in[2];
    const float* Wq = (const float*)d_in[3];
    const float* bq = (const float*)d_in[4];
    const float* Wk = (const float*)d_in[5];
    const float* bk = (const float*)d_in[6];
    const float* Wv = (const float*)d_in[7];
    const float* bv = (const float*)d_in[8];
    float* out = (float*)d_out;

    (void)in_sizes; (void)n_in;

    static const size_t OUT_ELEMS = (size_t)B * N * DH;          // 262144
    static const size_t E_ELEMS   = (size_t)B * N * N * 32;      // 67108864

    cudaFuncSetAttribute(attn_kernel, cudaFuncAttributeMaxDynamicSharedMemorySize,
                         SMEM_FLOATS * (int)sizeof(float));

    // e passthrough (second tuple output) — pure D2D copy, dominates runtime.
    cudaMemcpyAsync(out + OUT_ELEMS, e, E_ELEMS * sizeof(float),
                    cudaMemcpyDeviceToDevice);

    qkv_kernel<<<B * N, 256>>>(x, mask, Wq, bq, Wk, bk, Wv, bv);
    attn_kernel<<<B * (N / BM), 256, SMEM_FLOATS * sizeof(float)>>>(mask, out);

    (void)out_size;
}